// round 7
// baseline (speedup 1.0000x reference)
#include <cuda_runtime.h>
#include <math.h>

#define BATCH 512
#define LEN   1024
#define NA    13
#define NBND  5

typedef unsigned long long ull;

__device__ float g_partial[1024 * 40];
__device__ float g_stats[40];
__device__ float g_T[10];
__device__ float g_S[BATCH * 64 * 10];

// ---- f32x2 helpers ----
__device__ __forceinline__ ull pack2(float lo, float hi) {
    ull r; asm("mov.b64 %0, {%1, %2};" : "=l"(r) : "f"(lo), "f"(hi)); return r;
}
__device__ __forceinline__ void unpack2(ull v, float& lo, float& hi) {
    asm("mov.b64 {%0, %1}, %2;" : "=f"(lo), "=f"(hi) : "l"(v));
}
__device__ __forceinline__ ull fma2(ull a, ull b, ull c) {
    ull d; asm("fma.rn.f32x2 %0, %1, %2, %3;" : "=l"(d) : "l"(a), "l"(b), "l"(c)); return d;
}

// ---------------------------------------------------------------------------
// K1: grid = BATCH*2*2 (batch, l-half, branch). 128 threads, 4 outputs each.
// One aligned LDG.128 per channel + shfl halo. Branch CTA computes D[5]+G[15].
// ---------------------------------------------------------------------------
__global__ __launch_bounds__(128) void k_stats(const float* __restrict__ src,
                                               const float* __restrict__ dw1,
                                               const float* __restrict__ dw2) {
    __shared__ float s_red[4 * 20];
    int bid = blockIdx.x;
    int br = bid & 1;
    int h  = (bid >> 1) & 1;
    int b  = bid >> 2;
    int tid = threadIdx.x, w = tid >> 5, lid = tid & 31;
    int l0 = h * 512 + tid * 4;
    const float* sb = src + b * 5 * 1024;

    float wt[5][5];
#pragma unroll
    for (int c = 0; c < 5; c++) {
        if (br == 0) {
#pragma unroll
            for (int k = 0; k < 5; k++) wt[c][k] = __ldg(&dw1[c * 5 + k]);
        } else {
#pragma unroll
            for (int k = 0; k < 3; k++) wt[c][k] = __ldg(&dw2[c * 3 + k]);
            wt[c][3] = 0.f; wt[c][4] = 0.f;
        }
    }

    float dd[5][4];
#pragma unroll
    for (int c = 0; c < 5; c++) {
        const float* p = sb + c * 1024 + l0;
        float4 m = *(const float4*)p;
        float xl0 = __shfl_up_sync(0xffffffffu, m.z, 1);
        float xl1 = __shfl_up_sync(0xffffffffu, m.w, 1);
        float xr0 = __shfl_down_sync(0xffffffffu, m.x, 1);
        float xr1 = __shfl_down_sync(0xffffffffu, m.y, 1);
        if (lid == 0)  { xl0 = (l0 >= 2) ? p[-2] : 0.f; xl1 = (l0 >= 1) ? p[-1] : 0.f; }
        if (lid == 31) { xr0 = (l0 + 4 < 1024) ? p[4] : 0.f; xr1 = (l0 + 5 < 1024) ? p[5] : 0.f; }
        float x[8] = {xl0, xl1, m.x, m.y, m.z, m.w, xr0, xr1};
        if (br == 0) {
#pragma unroll
            for (int j = 0; j < 4; j++) {
                float a = 0.f;
#pragma unroll
                for (int k = 0; k < 5; k++) a = fmaf(wt[c][k], x[j + k], a);
                dd[c][j] = a;
            }
        } else {
#pragma unroll
            for (int j = 0; j < 4; j++) {
                float a = 0.f;
#pragma unroll
                for (int k = 0; k < 3; k++) a = fmaf(wt[c][k], x[j + k + 1], a);
                dd[c][j] = a;
            }
        }
    }

    float v[20];
#pragma unroll
    for (int j = 0; j < 20; j++) v[j] = 0.f;
#pragma unroll
    for (int j = 0; j < 4; j++) {
#pragma unroll
        for (int c = 0; c < 5; c++) v[c] += dd[c][j];
        int gi = 0;
#pragma unroll
        for (int c = 0; c < 5; c++)
#pragma unroll
            for (int c2 = c; c2 < 5; c2++, gi++)
                v[5 + gi] = fmaf(dd[c][j], dd[c2][j], v[5 + gi]);
    }

#pragma unroll
    for (int j = 0; j < 20; j++) {
#pragma unroll
        for (int off = 16; off > 0; off >>= 1)
            v[j] += __shfl_xor_sync(0xffffffffu, v[j], off);
    }
    if (lid == 0) {
#pragma unroll
        for (int j = 0; j < 20; j++) s_red[w * 20 + j] = v[j];
    }
    __syncthreads();
    if (tid < 20) {
        float s = s_red[tid] + s_red[20 + tid] + s_red[40 + tid] + s_red[60 + tid];
        g_partial[(b * 2 + h) * 40 + br * 20 + tid] = s;
    }
}

// ---------------------------------------------------------------------------
// K2: grid=50. Blocks 0..39 reduce g_partial -> g_stats; 40..49 compute T.
// ---------------------------------------------------------------------------
__global__ __launch_bounds__(128) void k_reduce(const float* __restrict__ flw) {
    __shared__ float s_w[4];
    int j = blockIdx.x, tid = threadIdx.x;
    float s = 0.f;
    if (j < 40) {
#pragma unroll
        for (int k = 0; k < 8; k++) s += g_partial[(tid + k * 128) * 40 + j];
    } else {
        int n = j - 40;
        const float* fp = flw + (n % 5) * 2048 + (n / 5) * 1024;
#pragma unroll
        for (int k = 0; k < 8; k++) s += __ldg(&fp[tid + k * 128]);
    }
#pragma unroll
    for (int off = 16; off > 0; off >>= 1) s += __shfl_xor_sync(0xffffffffu, s, off);
    if ((tid & 31) == 0) s_w[tid >> 5] = s;
    __syncthreads();
    if (tid == 0) {
        float r = s_w[0] + s_w[1] + s_w[2] + s_w[3];
        if (j < 40) g_stats[j] = r;
        else        g_T[j - 40] = r;
    }
}

// ---------------------------------------------------------------------------
// K3: per-branch main kernel. grid = BATCH*2, 256 threads, ~103KB smem
// (2 CTAs/SM). Computes S half -> g_S.
// ---------------------------------------------------------------------------
#define SM_SRC 0                          // 5*1032
#define SM_D   (5 * 1032)                 // 5*1024 float2 (dc, src)
#define SM_F2  (SM_D + 10240)             // 5*1024 float2 (F[2p], F[2p+1])
#define SM_ST  (SM_F2 + 10240)            // 20 raw stats (own branch)
#define SM_SC  (SM_ST + 20)               // 32 bn scale
#define SM_SH  (SM_SC + 32)               // 32 bn shift
#define SMEM_FLOATS (SM_SH + 32)
#define SMEM_BYTES  (SMEM_FLOATS * 4)

__global__ __launch_bounds__(256, 2) void k_main(
    const float* __restrict__ src,
    const float* __restrict__ dw1, const float* __restrict__ dw2,
    const float* __restrict__ pw1, const float* __restrict__ pw2,
    const float* __restrict__ g1, const float* __restrict__ be1,
    const float* __restrict__ g2, const float* __restrict__ be2,
    const float* __restrict__ r1w, const float* __restrict__ r1b,
    const float* __restrict__ r2w, const float* __restrict__ r2b,
    const float* __restrict__ flw) {
    extern __shared__ float sm[];
    int bid = blockIdx.x;
    int br = bid & 1;
    int b  = bid >> 1;
    int tid = threadIdx.x;
    int w = tid >> 5, lid = tid & 31;

    const float* pwp = br ? pw2 : pw1;
    const float* rwp = br ? r2w : r1w;
    const float* rbp = br ? r2b : r1b;
    const float* dwp = br ? dw2 : dw1;
    const float* gp  = br ? g2 : g1;
    const float* bep = br ? be2 : be1;

    // ---- stage 1: src halo, F2 pairs, own stats ----
    for (int idx = tid; idx < 5 * 1032; idx += 256) {
        int c = idx / 1032, p = idx - c * 1032;
        float v = 0.f;
        if (p >= 2 && p < 1026) v = src[(b * 5 + c) * 1024 + (p - 2)];
        sm[SM_SRC + idx] = v;
    }
    {
        ull* f2 = (ull*)(sm + SM_F2);
        for (int idx = tid; idx < 5 * 1024; idx += 256) {
            int p = idx >> 10, l = idx & 1023;
            int n0 = 2 * p, n1 = 2 * p + 1;
            float v0 = __ldg(&flw[(n0 % 5) * 2048 + (n0 / 5) * 1024 + l]);
            float v1 = __ldg(&flw[(n1 % 5) * 2048 + (n1 / 5) * 1024 + l]);
            f2[idx] = pack2(v0, v1);
        }
    }
    if (tid < 20) sm[SM_ST + tid] = g_stats[br * 20 + tid];
    __syncthreads();

    // ---- stage 2: own-branch depthwise (interleave with src); bn finalize ----
    {
        ull* d = (ull*)(sm + SM_D);
        float wt[5][5];
#pragma unroll
        for (int c = 0; c < 5; c++) {
            if (br == 0) {
#pragma unroll
                for (int k = 0; k < 5; k++) wt[c][k] = __ldg(&dwp[c * 5 + k]);
            } else {
#pragma unroll
                for (int k = 0; k < 3; k++) wt[c][k] = __ldg(&dwp[c * 3 + k]);
                wt[c][3] = 0.f; wt[c][4] = 0.f;
            }
        }
#pragma unroll
        for (int i = 0; i < 20; i++) {
            int idx = tid + i * 256;
            int c = idx >> 10, l = idx & 1023;
            const float* sp = &sm[SM_SRC + c * 1032 + l];
            float a;
            if (br == 0) {
                a = 0.f;
#pragma unroll
                for (int k = 0; k < 5; k++) a = fmaf(wt[c][k], sp[k], a);
            } else {
                a = 0.f;
#pragma unroll
                for (int k = 0; k < 3; k++) a = fmaf(wt[c][k], sp[k + 1], a);
            }
            d[idx] = pack2(a, sp[2]);
        }

        if (tid < 32) {
            int oc = tid;
            float pc[5];
            float m = 0.f;
#pragma unroll
            for (int c = 0; c < 5; c++) {
                pc[c] = __ldg(&pwp[oc * 5 + c]);
                m = fmaf(pc[c], sm[SM_ST + c], m);
            }
            const float invN = 1.f / (float)(BATCH * LEN);
            m *= invN;
            float e2 = 0.f;
            int gi = 0;
#pragma unroll
            for (int c = 0; c < 5; c++)
#pragma unroll
                for (int c2 = c; c2 < 5; c2++, gi++) {
                    float mult = (c == c2) ? 1.f : 2.f;
                    e2 = fmaf(mult * pc[c] * pc[c2], sm[SM_ST + 5 + gi], e2);
                }
            e2 *= invN;
            float var = e2 - m * m;
            float sc = __ldg(&gp[oc]) * rsqrtf(var + 1e-5f);
            sm[SM_SC + oc] = sc;
            sm[SM_SH + oc] = __ldg(&bep[oc]) - m * sc;
        }
    }
    __syncthreads();

    // ---- stage 3: 8 warps x 4 channels, full L, FFMA2 ----
    {
        int o0 = 4 * w;                    // local channel 0..28
        const ull* dsrc = (const ull*)(sm + SM_D);
        const ull* f2   = (const ull*)(sm + SM_F2);

        ull pr[4][5], shrb[4];
#pragma unroll
        for (int u = 0; u < 4; u++) {
            int oc = o0 + u;
            float sc = sm[SM_SC + oc];
#pragma unroll
            for (int c = 0; c < 5; c++)
                pr[u][c] = pack2(sc * __ldg(&pwp[oc * 5 + c]), __ldg(&rwp[oc * 5 + c]));
            shrb[u] = pack2(sm[SM_SH + oc], __ldg(&rbp[oc]));
        }

        ull acc[4][5];
#pragma unroll
        for (int u = 0; u < 4; u++)
#pragma unroll
            for (int p = 0; p < 5; p++) acc[u][p] = 0ULL;

#pragma unroll 1
        for (int it = 0; it < 32; it++) {
            int l = lid + it * 32;
            ull ds[5];
#pragma unroll
            for (int c = 0; c < 5; c++) ds[c] = dsrc[c * 1024 + l];
            ull t[4];
#pragma unroll
            for (int u = 0; u < 4; u++) t[u] = fma2(pr[u][0], ds[0], shrb[u]);
#pragma unroll
            for (int c = 1; c < 5; c++)
#pragma unroll
                for (int u = 0; u < 4; u++) t[u] = fma2(pr[u][c], ds[c], t[u]);
#pragma unroll
            for (int u = 0; u < 4; u++) {
                float y, z;
                unpack2(t[u], y, z);
                float xv = fmaxf(y, 0.f) * z;
                t[u] = pack2(xv, xv);
            }
#pragma unroll
            for (int p = 0; p < 5; p++) {
                ull f = f2[p * 1024 + l];
#pragma unroll
                for (int u = 0; u < 4; u++) acc[u][p] = fma2(t[u], f, acc[u][p]);
            }
        }

        float a[40];
#pragma unroll
        for (int u = 0; u < 4; u++)
#pragma unroll
            for (int p = 0; p < 5; p++)
                unpack2(acc[u][p], a[u * 10 + 2 * p], a[u * 10 + 2 * p + 1]);
#pragma unroll
        for (int j = 0; j < 40; j++) {
#pragma unroll
            for (int off = 16; off > 0; off >>= 1)
                a[j] += __shfl_xor_sync(0xffffffffu, a[j], off);
        }
        // S rows for global channels br*32 + o0 .. +3
        float* sp = g_S + (b * 64 + br * 32 + o0) * 10;
        if (lid == 0) {
#pragma unroll
            for (int j = 0; j < 20; j++) sp[j] = a[j];
        } else if (lid == 1) {
#pragma unroll
            for (int j = 20; j < 40; j++) sp[j] = a[j];
        }
    }
}

// ---------------------------------------------------------------------------
// K4: per-batch output. PQ[a,n] = ll1w·S + ll1b·T; out = PQ[mn,n]+PQ[mx,5+n]+flb
// ---------------------------------------------------------------------------
__global__ __launch_bounds__(256) void k_out(
    const float* __restrict__ ll1w, const float* __restrict__ ll1b,
    const float* __restrict__ flb, float* __restrict__ out) {
    __shared__ float s_S[640];
    __shared__ float s_L[NA * 64];
    __shared__ float s_PQ[130];
    int b = blockIdx.x, tid = threadIdx.x;

    for (int i = tid; i < 640; i += 256) s_S[i] = g_S[b * 640 + i];
    for (int i = tid; i < NA * 64; i += 256) s_L[i] = __ldg(&ll1w[i]);
    __syncthreads();

    if (tid < 130) {
        int a = tid / 10, n = tid - a * 10;
        float p = __ldg(&ll1b[a]) * g_T[n];
#pragma unroll 8
        for (int c = 0; c < 64; c++) p = fmaf(s_L[a * 64 + c], s_S[c * 10 + n], p);
        s_PQ[tid] = p;
    }
    __syncthreads();

    float* outp = out + b * (NA * NA * NBND);
    for (int t = tid; t < NA * NA * NBND; t += 256) {
        int i = t / (NA * NBND);
        int r = t - i * (NA * NBND);
        int j = r / NBND;
        int n = r - j * NBND;
        int mn = min(i, j), mx = max(i, j);
        outp[t] = s_PQ[mn * 10 + n] + s_PQ[mx * 10 + 5 + n] + __ldg(&flb[n]);
    }
}

// ---------------------------------------------------------------------------
extern "C" void kernel_launch(void* const* d_in, const int* in_sizes, int n_in,
                              void* d_out, int out_size) {
    const float* src  = (const float*)d_in[0];
    const float* dw1  = (const float*)d_in[3];
    const float* pw1  = (const float*)d_in[4];
    const float* g1   = (const float*)d_in[5];
    const float* be1  = (const float*)d_in[6];
    const float* r1w  = (const float*)d_in[7];
    const float* r1b  = (const float*)d_in[8];
    const float* dw2  = (const float*)d_in[9];
    const float* pw2  = (const float*)d_in[10];
    const float* g2   = (const float*)d_in[11];
    const float* be2  = (const float*)d_in[12];
    const float* r2w  = (const float*)d_in[13];
    const float* r2b  = (const float*)d_in[14];
    const float* ll1w = (const float*)d_in[15];
    const float* ll1b = (const float*)d_in[16];
    const float* flw  = (const float*)d_in[17];
    const float* flb  = (const float*)d_in[18];
    float* out = (float*)d_out;

    cudaFuncSetAttribute(k_main, cudaFuncAttributeMaxDynamicSharedMemorySize, SMEM_BYTES);

    k_stats<<<BATCH * 4, 128>>>(src, dw1, dw2);
    k_reduce<<<50, 128>>>(flw);
    k_main<<<BATCH * 2, 256, SMEM_BYTES>>>(src, dw1, dw2, pw1, pw2, g1, be1, g2, be2,
                                           r1w, r1b, r2w, r2b, flw);
    k_out<<<BATCH, 256>>>(ll1w, ll1b, flb, out);
}

// round 8
// speedup vs baseline: 1.0211x; 1.0211x over previous
#include <cuda_runtime.h>
#include <math.h>

#define BATCH 512
#define LEN   1024
#define NA    13
#define NBND  5

typedef unsigned long long ull;

__device__ float g_partial[1024 * 40];
__device__ float g_stats[40];
__device__ float g_T[10];
__device__ __align__(16) ull g_F2[5120];   // interleaved F pairs: [p][l] = (F[2p][l], F[2p+1][l])

// ---- f32x2 helpers ----
__device__ __forceinline__ ull pack2(float lo, float hi) {
    ull r; asm("mov.b64 %0, {%1, %2};" : "=l"(r) : "f"(lo), "f"(hi)); return r;
}
__device__ __forceinline__ void unpack2(ull v, float& lo, float& hi) {
    asm("mov.b64 {%0, %1}, %2;" : "=f"(lo), "=f"(hi) : "l"(v));
}
__device__ __forceinline__ ull fma2(ull a, ull b, ull c) {
    ull d; asm("fma.rn.f32x2 %0, %1, %2, %3;" : "=l"(d) : "l"(a), "l"(b), "l"(c)); return d;
}

// ---------------------------------------------------------------------------
// K1: grid = BATCH*2*2 (batch, l-half, branch). 128 threads, 4 outputs each.
// Aligned LDG.128 + shfl halo; per-branch D[5]+G[15].
// ---------------------------------------------------------------------------
__global__ __launch_bounds__(128) void k_stats(const float* __restrict__ src,
                                               const float* __restrict__ dw1,
                                               const float* __restrict__ dw2) {
    __shared__ float s_red[4 * 20];
    int bid = blockIdx.x;
    int br = bid & 1;
    int h  = (bid >> 1) & 1;
    int b  = bid >> 2;
    int tid = threadIdx.x, w = tid >> 5, lid = tid & 31;
    int l0 = h * 512 + tid * 4;
    const float* sb = src + b * 5 * 1024;

    float wt[5][5];
#pragma unroll
    for (int c = 0; c < 5; c++) {
        if (br == 0) {
#pragma unroll
            for (int k = 0; k < 5; k++) wt[c][k] = __ldg(&dw1[c * 5 + k]);
        } else {
#pragma unroll
            for (int k = 0; k < 3; k++) wt[c][k] = __ldg(&dw2[c * 3 + k]);
            wt[c][3] = 0.f; wt[c][4] = 0.f;
        }
    }

    float dd[5][4];
#pragma unroll
    for (int c = 0; c < 5; c++) {
        const float* p = sb + c * 1024 + l0;
        float4 m = *(const float4*)p;
        float xl0 = __shfl_up_sync(0xffffffffu, m.z, 1);
        float xl1 = __shfl_up_sync(0xffffffffu, m.w, 1);
        float xr0 = __shfl_down_sync(0xffffffffu, m.x, 1);
        float xr1 = __shfl_down_sync(0xffffffffu, m.y, 1);
        if (lid == 0)  { xl0 = (l0 >= 2) ? p[-2] : 0.f; xl1 = (l0 >= 1) ? p[-1] : 0.f; }
        if (lid == 31) { xr0 = (l0 + 4 < 1024) ? p[4] : 0.f; xr1 = (l0 + 5 < 1024) ? p[5] : 0.f; }
        float x[8] = {xl0, xl1, m.x, m.y, m.z, m.w, xr0, xr1};
        if (br == 0) {
#pragma unroll
            for (int j = 0; j < 4; j++) {
                float a = 0.f;
#pragma unroll
                for (int k = 0; k < 5; k++) a = fmaf(wt[c][k], x[j + k], a);
                dd[c][j] = a;
            }
        } else {
#pragma unroll
            for (int j = 0; j < 4; j++) {
                float a = 0.f;
#pragma unroll
                for (int k = 0; k < 3; k++) a = fmaf(wt[c][k], x[j + k + 1], a);
                dd[c][j] = a;
            }
        }
    }

    float v[20];
#pragma unroll
    for (int j = 0; j < 20; j++) v[j] = 0.f;
#pragma unroll
    for (int j = 0; j < 4; j++) {
#pragma unroll
        for (int c = 0; c < 5; c++) v[c] += dd[c][j];
        int gi = 0;
#pragma unroll
        for (int c = 0; c < 5; c++)
#pragma unroll
            for (int c2 = c; c2 < 5; c2++, gi++)
                v[5 + gi] = fmaf(dd[c][j], dd[c2][j], v[5 + gi]);
    }

#pragma unroll
    for (int j = 0; j < 20; j++) {
#pragma unroll
        for (int off = 16; off > 0; off >>= 1)
            v[j] += __shfl_xor_sync(0xffffffffu, v[j], off);
    }
    if (lid == 0) {
#pragma unroll
        for (int j = 0; j < 20; j++) s_red[w * 20 + j] = v[j];
    }
    __syncthreads();
    if (tid < 20) {
        float s = s_red[tid] + s_red[20 + tid] + s_red[40 + tid] + s_red[60 + tid];
        g_partial[(b * 2 + h) * 40 + br * 20 + tid] = s;
    }
}

// ---------------------------------------------------------------------------
// K2: grid=58. j<40: reduce stats; 40..49: T[n]; 50..57: build interleaved g_F2.
// ---------------------------------------------------------------------------
__global__ __launch_bounds__(128) void k_reduce(const float* __restrict__ flw) {
    __shared__ float s_w[4];
    int j = blockIdx.x, tid = threadIdx.x;

    if (j >= 50) {
        int base = (j - 50) * 640;
#pragma unroll
        for (int k = 0; k < 5; k++) {
            int idx = base + k * 128 + tid;
            int p = idx >> 10, l = idx & 1023;
            int n0 = 2 * p, n1 = 2 * p + 1;
            float v0 = __ldg(&flw[(n0 % 5) * 2048 + (n0 / 5) * 1024 + l]);
            float v1 = __ldg(&flw[(n1 % 5) * 2048 + (n1 / 5) * 1024 + l]);
            g_F2[idx] = pack2(v0, v1);
        }
        return;
    }

    float s = 0.f;
    if (j < 40) {
#pragma unroll
        for (int k = 0; k < 8; k++) s += g_partial[(tid + k * 128) * 40 + j];
    } else {
        int n = j - 40;
        const float* fp = flw + (n % 5) * 2048 + (n / 5) * 1024;
#pragma unroll
        for (int k = 0; k < 8; k++) s += __ldg(&fp[tid + k * 128]);
    }
#pragma unroll
    for (int off = 16; off > 0; off >>= 1) s += __shfl_xor_sync(0xffffffffu, s, off);
    if ((tid & 31) == 0) s_w[tid >> 5] = s;
    __syncthreads();
    if (tid == 0) {
        float r = s_w[0] + s_w[1] + s_w[2] + s_w[3];
        if (j < 40) g_stats[j] = r;
        else        g_T[j - 40] = r;
    }
}

// ---------------------------------------------------------------------------
// K3: fused main kernel. 512 threads, 1 block per batch, stages 1-5 inline.
// ---------------------------------------------------------------------------
#define SM_SRC 0                          // 5*1032
#define SM_D1  (5 * 1032)                 // 5*1024 float2 (dc1, src)
#define SM_D2  (SM_D1 + 10240)            // 5*1024 float2 (dc2, src)
#define SM_F2  (SM_D2 + 10240)            // 5*1024 float2
#define SM_L   (SM_F2 + 10240)            // 13*64  ll1w
#define SM_S   (SM_L + 832)               // 64*10
#define SM_PQ  (SM_S + 640)               // 13*10
#define SM_ST  (SM_PQ + 130)              // 40 stats
#define SM_SC  (SM_ST + 40)               // 64 scale
#define SM_SH  (SM_SC + 64)               // 64 shift
#define SMEM_FLOATS (SM_SH + 64)
#define SMEM_BYTES  (SMEM_FLOATS * 4)

__global__ __launch_bounds__(512, 1) void k_main(
    const float* __restrict__ src,
    const float* __restrict__ dw1, const float* __restrict__ dw2,
    const float* __restrict__ pw1, const float* __restrict__ pw2,
    const float* __restrict__ g1, const float* __restrict__ be1,
    const float* __restrict__ g2, const float* __restrict__ be2,
    const float* __restrict__ r1w, const float* __restrict__ r1b,
    const float* __restrict__ r2w, const float* __restrict__ r2b,
    const float* __restrict__ ll1w, const float* __restrict__ ll1b,
    const float* __restrict__ flb, float* __restrict__ out) {
    extern __shared__ float sm[];
    int b = blockIdx.x, tid = threadIdx.x;
    int w = tid >> 5, lid = tid & 31;

    // ---- stage 1: src halo, F2 copy (vectorized), ll1w, stats ----
    for (int idx = tid; idx < 5 * 1032; idx += 512) {
        int c = idx / 1032, p = idx - c * 1032;
        float v = 0.f;
        if (p >= 2 && p < 1026) v = src[(b * 5 + c) * 1024 + (p - 2)];
        sm[SM_SRC + idx] = v;
    }
    {
        uint4* dst = (uint4*)(sm + SM_F2);
        const uint4* srcf = (const uint4*)g_F2;
#pragma unroll
        for (int k = 0; k < 5; k++) dst[tid + k * 512] = __ldg(&srcf[tid + k * 512]);
    }
    for (int idx = tid; idx < NA * 64; idx += 512) sm[SM_L + idx] = __ldg(&ll1w[idx]);
    if (tid < 40) sm[SM_ST + tid] = g_stats[tid];
    __syncthreads();

    // ---- stage 2: depthwise, 4 outputs/item via LDS.128 window; bn finalize ----
    {
        ull* d1 = (ull*)(sm + SM_D1);
        ull* d2 = (ull*)(sm + SM_D2);
        float w1[5][5], w2[5][3];
#pragma unroll
        for (int c = 0; c < 5; c++) {
#pragma unroll
            for (int k = 0; k < 5; k++) w1[c][k] = __ldg(&dw1[c * 5 + k]);
#pragma unroll
            for (int k = 0; k < 3; k++) w2[c][k] = __ldg(&dw2[c * 3 + k]);
        }
#pragma unroll
        for (int i = 0; i < 5; i++) {
            int item = tid + i * 512;             // 0..2559
            int row = item >> 8;                  // 0..9
            int l0 = (item & 255) << 2;
            int c = (row < 5) ? row : row - 5;
            const float* base = &sm[SM_SRC + c * 1032 + l0];
            float4 fa = *(const float4*)base;
            float4 fb = *(const float4*)(base + 4);
            float x[8] = {fa.x, fa.y, fa.z, fa.w, fb.x, fb.y, fb.z, fb.w};
            ull q[4];
            if (row < 5) {
#pragma unroll
                for (int j = 0; j < 4; j++) {
                    float a = 0.f;
#pragma unroll
                    for (int k = 0; k < 5; k++) a = fmaf(w1[c][k], x[j + k], a);
                    q[j] = pack2(a, x[j + 2]);
                }
                uint4* dp = (uint4*)&d1[c * 1024 + l0];
                dp[0] = make_uint4((unsigned)q[0], (unsigned)(q[0] >> 32),
                                   (unsigned)q[1], (unsigned)(q[1] >> 32));
                dp[1] = make_uint4((unsigned)q[2], (unsigned)(q[2] >> 32),
                                   (unsigned)q[3], (unsigned)(q[3] >> 32));
            } else {
#pragma unroll
                for (int j = 0; j < 4; j++) {
                    float a = 0.f;
#pragma unroll
                    for (int k = 0; k < 3; k++) a = fmaf(w2[c][k], x[j + k + 1], a);
                    q[j] = pack2(a, x[j + 2]);
                }
                uint4* dp = (uint4*)&d2[c * 1024 + l0];
                dp[0] = make_uint4((unsigned)q[0], (unsigned)(q[0] >> 32),
                                   (unsigned)q[1], (unsigned)(q[1] >> 32));
                dp[1] = make_uint4((unsigned)q[2], (unsigned)(q[2] >> 32),
                                   (unsigned)q[3], (unsigned)(q[3] >> 32));
            }
        }

        // bn finalize: threads 0..63
        if (tid < 64) {
            int o = tid;
            bool br1 = (o < 32);
            int oc = br1 ? o : o - 32;
            const float* pw = br1 ? pw1 : pw2;
            int db = br1 ? 0 : 20;
            float pc[5];
            float m = 0.f;
#pragma unroll
            for (int c = 0; c < 5; c++) {
                pc[c] = __ldg(&pw[oc * 5 + c]);
                m = fmaf(pc[c], sm[SM_ST + db + c], m);
            }
            const float invN = 1.f / (float)(BATCH * LEN);
            m *= invN;
            float e2 = 0.f;
            int gi = 0;
#pragma unroll
            for (int c = 0; c < 5; c++)
#pragma unroll
                for (int c2 = c; c2 < 5; c2++, gi++) {
                    float mult = (c == c2) ? 1.f : 2.f;
                    e2 = fmaf(mult * pc[c] * pc[c2], sm[SM_ST + db + 5 + gi], e2);
                }
            e2 *= invN;
            float var = e2 - m * m;
            float gg = br1 ? __ldg(&g1[oc]) : __ldg(&g2[oc]);
            float bb = br1 ? __ldg(&be1[oc]) : __ldg(&be2[oc]);
            float sc = gg * rsqrtf(var + 1e-5f);
            sm[SM_SC + o] = sc;
            sm[SM_SH + o] = bb - m * sc;
        }
    }
    __syncthreads();

    // ---- stage 3: 16 warps x 4 channels, full L, FFMA2 ----
    {
        int o0 = 4 * w;
        bool br1 = (w < 8);
        int oc0 = br1 ? o0 : o0 - 32;
        const float* pwp = br1 ? pw1 : pw2;
        const float* rwp = br1 ? r1w : r2w;
        const float* rbp = br1 ? r1b : r2b;
        const ull* dsrc = (const ull*)(sm + (br1 ? SM_D1 : SM_D2));
        const ull* f2 = (const ull*)(sm + SM_F2);

        ull pr[4][5], shrb[4];
#pragma unroll
        for (int u = 0; u < 4; u++) {
            int o = o0 + u, oc = oc0 + u;
            float sc = sm[SM_SC + o];
#pragma unroll
            for (int c = 0; c < 5; c++)
                pr[u][c] = pack2(sc * __ldg(&pwp[oc * 5 + c]), __ldg(&rwp[oc * 5 + c]));
            shrb[u] = pack2(sm[SM_SH + o], __ldg(&rbp[oc]));
        }

        ull acc[4][5];
#pragma unroll
        for (int u = 0; u < 4; u++)
#pragma unroll
            for (int p = 0; p < 5; p++) acc[u][p] = 0ULL;

#pragma unroll 1
        for (int it = 0; it < 32; it++) {
            int l = lid + it * 32;
            ull ds[5];
#pragma unroll
            for (int c = 0; c < 5; c++) ds[c] = dsrc[c * 1024 + l];
            ull t[4];
#pragma unroll
            for (int u = 0; u < 4; u++) t[u] = fma2(pr[u][0], ds[0], shrb[u]);
#pragma unroll
            for (int c = 1; c < 5; c++)
#pragma unroll
                for (int u = 0; u < 4; u++) t[u] = fma2(pr[u][c], ds[c], t[u]);
#pragma unroll
            for (int u = 0; u < 4; u++) {
                float y, z;
                unpack2(t[u], y, z);
                float xv = fmaxf(y, 0.f) * z;
                t[u] = pack2(xv, xv);
            }
#pragma unroll
            for (int p = 0; p < 5; p++) {
                ull f = f2[p * 1024 + l];
#pragma unroll
                for (int u = 0; u < 4; u++) acc[u][p] = fma2(t[u], f, acc[u][p]);
            }
        }

        float a[40];
#pragma unroll
        for (int u = 0; u < 4; u++)
#pragma unroll
            for (int p = 0; p < 5; p++)
                unpack2(acc[u][p], a[u * 10 + 2 * p], a[u * 10 + 2 * p + 1]);
#pragma unroll
        for (int j = 0; j < 40; j++) {
#pragma unroll
            for (int off = 16; off > 0; off >>= 1)
                a[j] += __shfl_xor_sync(0xffffffffu, a[j], off);
        }
        if (lid == 0) {
#pragma unroll
            for (int j = 0; j < 20; j++) sm[SM_S + o0 * 10 + j] = a[j];
        } else if (lid == 1) {
#pragma unroll
            for (int j = 20; j < 40; j++) sm[SM_S + o0 * 10 + j] = a[j];
        }
    }
    __syncthreads();

    // ---- stage 4: PQ[a][n] = sum_c ll1w[a,c]*S[c,n] + ll1b[a]*T[n] ----
    if (tid < 130) {
        int a = tid / 10, n = tid - a * 10;
        float p = __ldg(&ll1b[a]) * g_T[n];
#pragma unroll 8
        for (int c = 0; c < 64; c++) p = fmaf(sm[SM_L + a * 64 + c], sm[SM_S + c * 10 + n], p);
        sm[SM_PQ + tid] = p;
    }
    __syncthreads();

    // ---- stage 5: out ----
    float* outp = out + b * (NA * NA * NBND);
    for (int t = tid; t < NA * NA * NBND; t += 512) {
        int i = t / (NA * NBND);
        int r = t - i * (NA * NBND);
        int j = r / NBND;
        int n = r - j * NBND;
        int mn = min(i, j), mx = max(i, j);
        outp[t] = sm[SM_PQ + mn * 10 + n] + sm[SM_PQ + mx * 10 + 5 + n] + __ldg(&flb[n]);
    }
}

// ---------------------------------------------------------------------------
extern "C" void kernel_launch(void* const* d_in, const int* in_sizes, int n_in,
                              void* d_out, int out_size) {
    const float* src  = (const float*)d_in[0];
    const float* dw1  = (const float*)d_in[3];
    const float* pw1  = (const float*)d_in[4];
    const float* g1   = (const float*)d_in[5];
    const float* be1  = (const float*)d_in[6];
    const float* r1w  = (const float*)d_in[7];
    const float* r1b  = (const float*)d_in[8];
    const float* dw2  = (const float*)d_in[9];
    const float* pw2  = (const float*)d_in[10];
    const float* g2   = (const float*)d_in[11];
    const float* be2  = (const float*)d_in[12];
    const float* r2w  = (const float*)d_in[13];
    const float* r2b  = (const float*)d_in[14];
    const float* ll1w = (const float*)d_in[15];
    const float* ll1b = (const float*)d_in[16];
    const float* flw  = (const float*)d_in[17];
    const float* flb  = (const float*)d_in[18];
    float* out = (float*)d_out;

    cudaFuncSetAttribute(k_main, cudaFuncAttributeMaxDynamicSharedMemorySize, SMEM_BYTES);

    k_stats<<<BATCH * 4, 128>>>(src, dw1, dw2);
    k_reduce<<<58, 128>>>(flw);
    k_main<<<BATCH, 512, SMEM_BYTES>>>(src, dw1, dw2, pw1, pw2, g1, be1, g2, be2,
                                       r1w, r1b, r2w, r2b, ll1w, ll1b, flb, out);
}

// round 9
// speedup vs baseline: 1.0432x; 1.0216x over previous
#include <cuda_runtime.h>
#include <math.h>

#define BATCH 512
#define LEN   1024
#define NA    13
#define NBND  5

typedef unsigned long long ull;

__device__ float g_partial[1024 * 40];
__device__ float g_stats[40];
__device__ float g_T[10];
__device__ __align__(16) ull g_F2[5120];   // interleaved F pairs: [p][l] = (F[2p][l], F[2p+1][l])

// ---- f32x2 helpers ----
__device__ __forceinline__ ull pack2(float lo, float hi) {
    ull r; asm("mov.b64 %0, {%1, %2};" : "=l"(r) : "f"(lo), "f"(hi)); return r;
}
__device__ __forceinline__ void unpack2(ull v, float& lo, float& hi) {
    asm("mov.b64 {%0, %1}, %2;" : "=f"(lo), "=f"(hi) : "l"(v));
}
__device__ __forceinline__ ull fma2(ull a, ull b, ull c) {
    ull d; asm("fma.rn.f32x2 %0, %1, %2, %3;" : "=l"(d) : "l"(a), "l"(b), "l"(c)); return d;
}

// ---------------------------------------------------------------------------
// K1: grid = BATCH*2 (batch, l-half). 128 threads, 4 positions each, BOTH
// branches from one src read. Aligned LDG.128 + shfl halo. One 40-val reduce.
// ---------------------------------------------------------------------------
__global__ __launch_bounds__(128) void k_stats(const float* __restrict__ src,
                                               const float* __restrict__ dw1,
                                               const float* __restrict__ dw2) {
    __shared__ float s_red[4 * 40];
    int bid = blockIdx.x;
    int h = bid & 1;
    int b = bid >> 1;
    int tid = threadIdx.x, w = tid >> 5, lid = tid & 31;
    int l0 = h * 512 + tid * 4;
    const float* sb = src + b * 5 * 1024;

    float w1[5][5], w2[5][3];
#pragma unroll
    for (int c = 0; c < 5; c++) {
#pragma unroll
        for (int k = 0; k < 5; k++) w1[c][k] = __ldg(&dw1[c * 5 + k]);
#pragma unroll
        for (int k = 0; k < 3; k++) w2[c][k] = __ldg(&dw2[c * 3 + k]);
    }

    float d1[5][4], d2[5][4];
#pragma unroll
    for (int c = 0; c < 5; c++) {
        const float* p = sb + c * 1024 + l0;
        float4 m = *(const float4*)p;
        float xl0 = __shfl_up_sync(0xffffffffu, m.z, 1);
        float xl1 = __shfl_up_sync(0xffffffffu, m.w, 1);
        float xr0 = __shfl_down_sync(0xffffffffu, m.x, 1);
        float xr1 = __shfl_down_sync(0xffffffffu, m.y, 1);
        if (lid == 0)  { xl0 = (l0 >= 2) ? p[-2] : 0.f; xl1 = (l0 >= 1) ? p[-1] : 0.f; }
        if (lid == 31) { xr0 = (l0 + 4 < 1024) ? p[4] : 0.f; xr1 = (l0 + 5 < 1024) ? p[5] : 0.f; }
        float x[8] = {xl0, xl1, m.x, m.y, m.z, m.w, xr0, xr1};
#pragma unroll
        for (int j = 0; j < 4; j++) {
            float a1 = 0.f;
#pragma unroll
            for (int k = 0; k < 5; k++) a1 = fmaf(w1[c][k], x[j + k], a1);
            d1[c][j] = a1;
            float a2 = 0.f;
#pragma unroll
            for (int k = 0; k < 3; k++) a2 = fmaf(w2[c][k], x[j + k + 1], a2);
            d2[c][j] = a2;
        }
    }

    // v[0..4]=D1, v[5..19]=G1, v[20..24]=D2, v[25..39]=G2
    float v[40];
#pragma unroll
    for (int j = 0; j < 40; j++) v[j] = 0.f;
#pragma unroll
    for (int j = 0; j < 4; j++) {
#pragma unroll
        for (int c = 0; c < 5; c++) { v[c] += d1[c][j]; v[20 + c] += d2[c][j]; }
        int gi = 0;
#pragma unroll
        for (int c = 0; c < 5; c++)
#pragma unroll
            for (int c2 = c; c2 < 5; c2++, gi++) {
                v[5 + gi]  = fmaf(d1[c][j], d1[c2][j], v[5 + gi]);
                v[25 + gi] = fmaf(d2[c][j], d2[c2][j], v[25 + gi]);
            }
    }

#pragma unroll
    for (int j = 0; j < 40; j++) {
#pragma unroll
        for (int off = 16; off > 0; off >>= 1)
            v[j] += __shfl_xor_sync(0xffffffffu, v[j], off);
    }
    if (lid == 0) {
#pragma unroll
        for (int j = 0; j < 40; j++) s_red[w * 40 + j] = v[j];
    }
    __syncthreads();
    if (tid < 40) {
        float s = s_red[tid] + s_red[40 + tid] + s_red[80 + tid] + s_red[120 + tid];
        g_partial[(b * 2 + h) * 40 + tid] = s;
    }
}

// ---------------------------------------------------------------------------
// K2: grid=58. j<40: reduce stats; 40..49: T[n]; 50..57: build interleaved g_F2.
// ---------------------------------------------------------------------------
__global__ __launch_bounds__(128) void k_reduce(const float* __restrict__ flw) {
    __shared__ float s_w[4];
    int j = blockIdx.x, tid = threadIdx.x;

    if (j >= 50) {
        int base = (j - 50) * 640;
#pragma unroll
        for (int k = 0; k < 5; k++) {
            int idx = base + k * 128 + tid;
            int p = idx >> 10, l = idx & 1023;
            int n0 = 2 * p, n1 = 2 * p + 1;
            float v0 = __ldg(&flw[(n0 % 5) * 2048 + (n0 / 5) * 1024 + l]);
            float v1 = __ldg(&flw[(n1 % 5) * 2048 + (n1 / 5) * 1024 + l]);
            g_F2[idx] = pack2(v0, v1);
        }
        return;
    }

    float s = 0.f;
    if (j < 40) {
#pragma unroll
        for (int k = 0; k < 8; k++) s += g_partial[(tid + k * 128) * 40 + j];
    } else {
        int n = j - 40;
        const float* fp = flw + (n % 5) * 2048 + (n / 5) * 1024;
#pragma unroll
        for (int k = 0; k < 8; k++) s += __ldg(&fp[tid + k * 128]);
    }
#pragma unroll
    for (int off = 16; off > 0; off >>= 1) s += __shfl_xor_sync(0xffffffffu, s, off);
    if ((tid & 31) == 0) s_w[tid >> 5] = s;
    __syncthreads();
    if (tid == 0) {
        float r = s_w[0] + s_w[1] + s_w[2] + s_w[3];
        if (j < 40) g_stats[j] = r;
        else        g_T[j - 40] = r;
    }
}

// ---------------------------------------------------------------------------
// K3: fused main kernel. 512 threads, 1 block per batch.
// src staged with stride 1040, left pad 4 -> fully aligned 128-bit copies.
// ---------------------------------------------------------------------------
#define SSTRIDE 1040
#define SM_SRC 0                          // 5*1040
#define SM_D1  (5 * SSTRIDE)              // 5*1024 float2 (dc1, src)
#define SM_D2  (SM_D1 + 10240)            // 5*1024 float2 (dc2, src)
#define SM_F2  (SM_D2 + 10240)            // 5*1024 float2
#define SM_L   (SM_F2 + 10240)            // 13*64  ll1w
#define SM_S   (SM_L + 832)               // 64*10
#define SM_PQ  (SM_S + 640)               // 13*10
#define SM_ST  (SM_PQ + 130)              // 40 stats
#define SM_SC  (SM_ST + 40)               // 64 scale
#define SM_SH  (SM_SC + 64)               // 64 shift
#define SMEM_FLOATS (SM_SH + 64)
#define SMEM_BYTES  (SMEM_FLOATS * 4)

__global__ __launch_bounds__(512, 1) void k_main(
    const float* __restrict__ src,
    const float* __restrict__ dw1, const float* __restrict__ dw2,
    const float* __restrict__ pw1, const float* __restrict__ pw2,
    const float* __restrict__ g1, const float* __restrict__ be1,
    const float* __restrict__ g2, const float* __restrict__ be2,
    const float* __restrict__ r1w, const float* __restrict__ r1b,
    const float* __restrict__ r2w, const float* __restrict__ r2b,
    const float* __restrict__ ll1w, const float* __restrict__ ll1b,
    const float* __restrict__ flb, float* __restrict__ out) {
    extern __shared__ float sm[];
    int b = blockIdx.x, tid = threadIdx.x;
    int w = tid >> 5, lid = tid & 31;

    // ---- stage 1: vectorized src staging (pad-4 layout), F2 copy, ll1w, stats ----
    {
        const float4* sb = (const float4*)(src + b * 5 * 1024);
        for (int idx = tid; idx < 1280; idx += 512) {
            int c = idx >> 8, l4 = idx & 255;
            *(float4*)&sm[SM_SRC + c * SSTRIDE + 4 + l4 * 4] = __ldg(&sb[c * 256 + l4]);
        }
        if (tid < 80) {                    // zero pads: 4 left + 12 right per channel
            int c = tid >> 4, r = tid & 15;
            int off = (r < 4) ? r : (1024 + r);
            sm[SM_SRC + c * SSTRIDE + off] = 0.f;
        }
    }
    {
        uint4* dst = (uint4*)(sm + SM_F2);
        const uint4* srcf = (const uint4*)g_F2;
#pragma unroll
        for (int k = 0; k < 5; k++) dst[tid + k * 512] = __ldg(&srcf[tid + k * 512]);
    }
    for (int idx = tid; idx < NA * 64; idx += 512) sm[SM_L + idx] = __ldg(&ll1w[idx]);
    if (tid < 40) sm[SM_ST + tid] = g_stats[tid];
    __syncthreads();

    // ---- stage 2: depthwise, 4 outputs/item via 3x LDS.128; bn finalize ----
    {
        ull* d1 = (ull*)(sm + SM_D1);
        ull* d2 = (ull*)(sm + SM_D2);
        float w1[5][5], w2[5][3];
#pragma unroll
        for (int c = 0; c < 5; c++) {
#pragma unroll
            for (int k = 0; k < 5; k++) w1[c][k] = __ldg(&dw1[c * 5 + k]);
#pragma unroll
            for (int k = 0; k < 3; k++) w2[c][k] = __ldg(&dw2[c * 3 + k]);
        }
#pragma unroll
        for (int i = 0; i < 5; i++) {
            int item = tid + i * 512;             // 0..2559
            int row = item >> 8;                  // 0..9
            int l0 = (item & 255) << 2;
            int c = (row < 5) ? row : row - 5;
            const float* base = &sm[SM_SRC + c * SSTRIDE + l0];   // padded[l0] = src[l0-4]
            float4 fa = *(const float4*)base;
            float4 fb = *(const float4*)(base + 4);
            float4 fc = *(const float4*)(base + 8);
            // xx[i] = src[l0 - 4 + i]
            float xx[12] = {fa.x, fa.y, fa.z, fa.w, fb.x, fb.y, fb.z, fb.w,
                            fc.x, fc.y, fc.z, fc.w};
            ull q[4];
            if (row < 5) {
#pragma unroll
                for (int j = 0; j < 4; j++) {     // needs src[l0+j-2 .. l0+j+2] = xx[2+j..6+j]
                    float a = 0.f;
#pragma unroll
                    for (int k = 0; k < 5; k++) a = fmaf(w1[c][k], xx[2 + j + k], a);
                    q[j] = pack2(a, xx[4 + j]);
                }
                uint4* dp = (uint4*)&d1[c * 1024 + l0];
                dp[0] = make_uint4((unsigned)q[0], (unsigned)(q[0] >> 32),
                                   (unsigned)q[1], (unsigned)(q[1] >> 32));
                dp[1] = make_uint4((unsigned)q[2], (unsigned)(q[2] >> 32),
                                   (unsigned)q[3], (unsigned)(q[3] >> 32));
            } else {
#pragma unroll
                for (int j = 0; j < 4; j++) {     // needs src[l0+j-1 .. l0+j+1] = xx[3+j..5+j]
                    float a = 0.f;
#pragma unroll
                    for (int k = 0; k < 3; k++) a = fmaf(w2[c][k], xx[3 + j + k], a);
                    q[j] = pack2(a, xx[4 + j]);
                }
                uint4* dp = (uint4*)&d2[c * 1024 + l0];
                dp[0] = make_uint4((unsigned)q[0], (unsigned)(q[0] >> 32),
                                   (unsigned)q[1], (unsigned)(q[1] >> 32));
                dp[1] = make_uint4((unsigned)q[2], (unsigned)(q[2] >> 32),
                                   (unsigned)q[3], (unsigned)(q[3] >> 32));
            }
        }

        // bn finalize: threads 0..63
        if (tid < 64) {
            int o = tid;
            bool br1 = (o < 32);
            int oc = br1 ? o : o - 32;
            const float* pw = br1 ? pw1 : pw2;
            int db = br1 ? 0 : 20;
            float pc[5];
            float m = 0.f;
#pragma unroll
            for (int c = 0; c < 5; c++) {
                pc[c] = __ldg(&pw[oc * 5 + c]);
                m = fmaf(pc[c], sm[SM_ST + db + c], m);
            }
            const float invN = 1.f / (float)(BATCH * LEN);
            m *= invN;
            float e2 = 0.f;
            int gi = 0;
#pragma unroll
            for (int c = 0; c < 5; c++)
#pragma unroll
                for (int c2 = c; c2 < 5; c2++, gi++) {
                    float mult = (c == c2) ? 1.f : 2.f;
                    e2 = fmaf(mult * pc[c] * pc[c2], sm[SM_ST + db + 5 + gi], e2);
                }
            e2 *= invN;
            float var = e2 - m * m;
            float gg = br1 ? __ldg(&g1[oc]) : __ldg(&g2[oc]);
            float bb = br1 ? __ldg(&be1[oc]) : __ldg(&be2[oc]);
            float sc = gg * rsqrtf(var + 1e-5f);
            sm[SM_SC + o] = sc;
            sm[SM_SH + o] = bb - m * sc;
        }
    }
    __syncthreads();

    // ---- stage 3: 16 warps x 4 channels, full L, FFMA2 ----
    {
        int o0 = 4 * w;
        bool br1 = (w < 8);
        int oc0 = br1 ? o0 : o0 - 32;
        const float* pwp = br1 ? pw1 : pw2;
        const float* rwp = br1 ? r1w : r2w;
        const float* rbp = br1 ? r1b : r2b;
        const ull* dsrc = (const ull*)(sm + (br1 ? SM_D1 : SM_D2));
        const ull* f2 = (const ull*)(sm + SM_F2);

        ull pr[4][5], shrb[4];
#pragma unroll
        for (int u = 0; u < 4; u++) {
            int o = o0 + u, oc = oc0 + u;
            float sc = sm[SM_SC + o];
#pragma unroll
            for (int c = 0; c < 5; c++)
                pr[u][c] = pack2(sc * __ldg(&pwp[oc * 5 + c]), __ldg(&rwp[oc * 5 + c]));
            shrb[u] = pack2(sm[SM_SH + o], __ldg(&rbp[oc]));
        }

        ull acc[4][5];
#pragma unroll
        for (int u = 0; u < 4; u++)
#pragma unroll
            for (int p = 0; p < 5; p++) acc[u][p] = 0ULL;

#pragma unroll 1
        for (int it = 0; it < 32; it++) {
            int l = lid + it * 32;
            ull ds[5];
#pragma unroll
            for (int c = 0; c < 5; c++) ds[c] = dsrc[c * 1024 + l];
            ull t[4];
#pragma unroll
            for (int u = 0; u < 4; u++) t[u] = fma2(pr[u][0], ds[0], shrb[u]);
#pragma unroll
            for (int c = 1; c < 5; c++)
#pragma unroll
                for (int u = 0; u < 4; u++) t[u] = fma2(pr[u][c], ds[c], t[u]);
#pragma unroll
            for (int u = 0; u < 4; u++) {
                float y, z;
                unpack2(t[u], y, z);
                float xv = fmaxf(y, 0.f) * z;
                t[u] = pack2(xv, xv);
            }
#pragma unroll
            for (int p = 0; p < 5; p++) {
                ull f = f2[p * 1024 + l];
#pragma unroll
                for (int u = 0; u < 4; u++) acc[u][p] = fma2(t[u], f, acc[u][p]);
            }
        }

        float a[40];
#pragma unroll
        for (int u = 0; u < 4; u++)
#pragma unroll
            for (int p = 0; p < 5; p++)
                unpack2(acc[u][p], a[u * 10 + 2 * p], a[u * 10 + 2 * p + 1]);
#pragma unroll
        for (int j = 0; j < 40; j++) {
#pragma unroll
            for (int off = 16; off > 0; off >>= 1)
                a[j] += __shfl_xor_sync(0xffffffffu, a[j], off);
        }
        if (lid == 0) {
#pragma unroll
            for (int j = 0; j < 20; j++) sm[SM_S + o0 * 10 + j] = a[j];
        } else if (lid == 1) {
#pragma unroll
            for (int j = 20; j < 40; j++) sm[SM_S + o0 * 10 + j] = a[j];
        }
    }
    __syncthreads();

    // ---- stage 4: PQ[a][n] = sum_c ll1w[a,c]*S[c,n] + ll1b[a]*T[n] ----
    if (tid < 130) {
        int a = tid / 10, n = tid - a * 10;
        float p = __ldg(&ll1b[a]) * g_T[n];
#pragma unroll 8
        for (int c = 0; c < 64; c++) p = fmaf(sm[SM_L + a * 64 + c], sm[SM_S + c * 10 + n], p);
        sm[SM_PQ + tid] = p;
    }
    __syncthreads();

    // ---- stage 5: out ----
    float* outp = out + b * (NA * NA * NBND);
    for (int t = tid; t < NA * NA * NBND; t += 512) {
        int i = t / (NA * NBND);
        int r = t - i * (NA * NBND);
        int j = r / NBND;
        int n = r - j * NBND;
        int mn = min(i, j), mx = max(i, j);
        outp[t] = sm[SM_PQ + mn * 10 + n] + sm[SM_PQ + mx * 10 + 5 + n] + __ldg(&flb[n]);
    }
}

// ---------------------------------------------------------------------------
extern "C" void kernel_launch(void* const* d_in, const int* in_sizes, int n_in,
                              void* d_out, int out_size) {
    const float* src  = (const float*)d_in[0];
    const float* dw1  = (const float*)d_in[3];
    const float* pw1  = (const float*)d_in[4];
    const float* g1   = (const float*)d_in[5];
    const float* be1  = (const float*)d_in[6];
    const float* r1w  = (const float*)d_in[7];
    const float* r1b  = (const float*)d_in[8];
    const float* dw2  = (const float*)d_in[9];
    const float* pw2  = (const float*)d_in[10];
    const float* g2   = (const float*)d_in[11];
    const float* be2  = (const float*)d_in[12];
    const float* r2w  = (const float*)d_in[13];
    const float* r2b  = (const float*)d_in[14];
    const float* ll1w = (const float*)d_in[15];
    const float* ll1b = (const float*)d_in[16];
    const float* flw  = (const float*)d_in[17];
    const float* flb  = (const float*)d_in[18];
    float* out = (float*)d_out;

    cudaFuncSetAttribute(k_main, cudaFuncAttributeMaxDynamicSharedMemorySize, SMEM_BYTES);

    k_stats<<<BATCH * 2, 128>>>(src, dw1, dw2);
    k_reduce<<<58, 128>>>(flw);
    k_main<<<BATCH, 512, SMEM_BYTES>>>(src, dw1, dw2, pw1, pw2, g1, be1, g2, be2,
                                       r1w, r1b, r2w, r2b, ll1w, ll1b, flb, out);
}